// round 13
// baseline (speedup 1.0000x reference)
#include <cuda_runtime.h>

// Shape (N,C,T,V,M) = (256,3,600,25,2), f32
#define NB      256
#define CC      3
#define TT      600
#define VV      25
#define ROWS    (CC * TT)          // 1800 rows of 50 floats per sample
#define F2_ROW  VV                 // 25 float2 per row (one float2 per joint)
#define F2_N    (ROWS * F2_ROW)    // 45000 float2 per sample
#define THREADS 500                // multiple of 25 -> fixed joint per thread
#define ROWS_IT (THREADS / VV)     // 20 rows per iteration
#define ITERS   (ROWS / ROWS_IT)   // 90 iterations
#define NTOT    23040000.0f

__device__ float        g_partial[NB];
__device__ unsigned int g_count;     // zero-init at module load; reset by last block

__global__ __launch_bounds__(THREADS, 2)
void loss_fused(const float2* __restrict__ x, const float2* __restrict__ y,
                float* __restrict__ out)
{
    const int n   = blockIdx.x;
    const int tid = threadIdx.x;
    const int v   = tid % VV;
    const int r0  = tid / VV;

    const float2* __restrict__ xn = x + (size_t)n * F2_N;
    const float2* __restrict__ yn = y + (size_t)n * F2_N;

    __shared__ float sAbs[VV];
    __shared__ float sSq[VV];
    __shared__ bool  sLast;
    if (tid < VV) { sAbs[tid] = 0.0f; sSq[tid] = 0.0f; }
    __syncthreads();

    float accA = 0.0f;   // sum |x[t+1]-x[t]|
    float accS = 0.0f;   // sum (x-y)^2

    #pragma unroll 9
    for (int j = 0; j < ITERS; ++j) {
        const int idx = tid + j * THREADS;
        const int row = r0  + j * ROWS_IT;
        const int t   = row % TT;

        const float2 a  = __ldg(&xn[idx]);
        const float2 yv = __ldcs(&yn[idx]);     // read-once stream: evict-first
        const float dx = a.x - yv.x;
        const float dy = a.y - yv.y;
        accS = fmaf(dx, dx, accS);
        accS = fmaf(dy, dy, accS);

        if (t != TT - 1) {                       // diff stays within channel c
            const float2 b = __ldg(&xn[idx + F2_ROW]);
            accA += fabsf(b.x - a.x) + fabsf(b.y - a.y);
        }
    }

    atomicAdd(&sAbs[v], accA);
    atomicAdd(&sSq[v],  accS);
    __syncthreads();

    // Warp 0: per-sample combine, publish partial, elect last block
    if (tid < 32) {
        float myAbs = (tid < VV) ? sAbs[tid] : 0.0f;
        float mySq  = (tid < VV) ? sSq[tid]  : 0.0f;

        float tot = myAbs;
        #pragma unroll
        for (int o = 16; o > 0; o >>= 1)
            tot += __shfl_xor_sync(0xffffffffu, tot, o);

        float contrib = myAbs * mySq;
        #pragma unroll
        for (int o = 16; o > 0; o >>= 1)
            contrib += __shfl_xor_sync(0xffffffffu, contrib, o);

        if (tid == 0) {
            g_partial[n] = (float)VV * contrib / tot;
            __threadfence();
            unsigned int prev = atomicAdd(&g_count, 1u);
            sLast = (prev == NB - 1);
        }
    }
    __syncthreads();

    // Last-arriving block: reduce all 256 partials (fixed order -> deterministic)
    if (sLast && tid < 32) {
        __threadfence();
        float val = 0.0f;
        #pragma unroll
        for (int k = 0; k < NB / 32; ++k)
            val += g_partial[tid + k * 32];
        #pragma unroll
        for (int o = 16; o > 0; o >>= 1)
            val += __shfl_xor_sync(0xffffffffu, val, o);
        if (tid == 0) {
            out[0]  = val / NTOT;
            g_count = 0u;            // rearm for next graph replay
            __threadfence();
        }
    }
}

extern "C" void kernel_launch(void* const* d_in, const int* in_sizes, int n_in,
                              void* d_out, int out_size)
{
    (void)in_sizes; (void)n_in; (void)out_size;
    loss_fused<<<NB, THREADS>>>((const float2*)d_in[0],
                                (const float2*)d_in[1],
                                (float*)d_out);
}

// round 14
// speedup vs baseline: 1.0504x; 1.0504x over previous
#include <cuda_runtime.h>

// Shape (N,C,T,V,M) = (256,3,600,25,2), f32
#define NB      256
#define CC      3
#define TT      600
#define VV      25
#define ROWS    (CC * TT)          // 1800 rows of 50 floats per sample
#define F2_ROW  VV                 // 25 float2 per row (one float2 per joint)
#define F2_N    (ROWS * F2_ROW)    // 45000 float2 per sample
#define THREADS 500                // multiple of 25 -> fixed joint per thread
#define ROWS_IT (THREADS / VV)     // 20 rows per iteration
#define ITERS   (ROWS / ROWS_IT)   // 90 iterations
#define NTOT    23040000.0f

__device__ float        g_partial[NB];
__device__ unsigned int g_count;     // zero-init at module load; reset by last block

__global__ __launch_bounds__(THREADS, 2)
void loss_fused(const float2* __restrict__ x, const float2* __restrict__ y,
                float* __restrict__ out)
{
    const int n   = blockIdx.x;
    const int tid = threadIdx.x;
    const int v   = tid % VV;
    const int r0  = tid / VV;

    const float2* __restrict__ xn = x + (size_t)n * F2_N;
    const float2* __restrict__ yn = y + (size_t)n * F2_N;

    __shared__ float sAbs[VV];
    __shared__ float sSq[VV];
    __shared__ bool  sLast;
    if (tid < VV) { sAbs[tid] = 0.0f; sSq[tid] = 0.0f; }
    __syncthreads();

    float accA = 0.0f;   // sum |x[t+1]-x[t]|
    float accS = 0.0f;   // sum (x-y)^2

    #pragma unroll 6
    for (int j = 0; j < ITERS; ++j) {
        const int idx = tid + j * THREADS;
        const int row = r0  + j * ROWS_IT;
        const int t   = row % TT;

        const float2 a  = __ldg(&xn[idx]);
        const float2 yv = __ldcs(&yn[idx]);     // read-once stream: evict-first
        const float dx = a.x - yv.x;
        const float dy = a.y - yv.y;
        accS = fmaf(dx, dx, accS);
        accS = fmaf(dy, dy, accS);

        if (t != TT - 1) {                       // diff stays within channel c
            const float2 b = __ldg(&xn[idx + F2_ROW]);
            accA += fabsf(b.x - a.x) + fabsf(b.y - a.y);
        }
    }

    atomicAdd(&sAbs[v], accA);
    atomicAdd(&sSq[v],  accS);
    __syncthreads();

    // Warp 0: per-sample combine, publish partial, elect last block
    if (tid < 32) {
        float myAbs = (tid < VV) ? sAbs[tid] : 0.0f;
        float mySq  = (tid < VV) ? sSq[tid]  : 0.0f;

        float tot = myAbs;
        #pragma unroll
        for (int o = 16; o > 0; o >>= 1)
            tot += __shfl_xor_sync(0xffffffffu, tot, o);

        float contrib = myAbs * mySq;
        #pragma unroll
        for (int o = 16; o > 0; o >>= 1)
            contrib += __shfl_xor_sync(0xffffffffu, contrib, o);

        if (tid == 0) {
            g_partial[n] = (float)VV * contrib / tot;
            __threadfence();
            unsigned int prev = atomicAdd(&g_count, 1u);
            sLast = (prev == NB - 1);
        }
    }
    __syncthreads();

    // Last-arriving block: reduce all 256 partials (fixed order -> deterministic)
    if (sLast && tid < 32) {
        __threadfence();
        float val = 0.0f;
        #pragma unroll
        for (int k = 0; k < NB / 32; ++k)
            val += g_partial[tid + k * 32];
        #pragma unroll
        for (int o = 16; o > 0; o >>= 1)
            val += __shfl_xor_sync(0xffffffffu, val, o);
        if (tid == 0) {
            out[0]  = val / NTOT;
            g_count = 0u;            // rearm for next graph replay
            __threadfence();
        }
    }
}

extern "C" void kernel_launch(void* const* d_in, const int* in_sizes, int n_in,
                              void* d_out, int out_size)
{
    (void)in_sizes; (void)n_in; (void)out_size;
    loss_fused<<<NB, THREADS>>>((const float2*)d_in[0],
                                (const float2*)d_in[1],
                                (float*)d_out);
}